// round 3
// baseline (speedup 1.0000x reference)
#include <cuda_runtime.h>
#include <cstdint>

// YOLO-v1 loss: pred/target (2048, 28, 28, 30) fp32 -> scalar fp32.
// Persistent blocks; PER-WARP decoupled 3-stage cp.async pipelines (no
// __syncthreads in main loop); thread-per-cell compute from smem via float2;
// per-thread accumulator; one atomicAdd per block.

#define CELLS    (2048 * 28 * 28)      // 1,605,632
#define CH       30
#define TPB      128
#define NW_BLK   (TPB / 32)            // 4 warps per block
#define GRID_B   296                   // 2 blocks/SM on 148 SMs
#define NWARPS   (GRID_B * NW_BLK)     // 1184 global warps
#define NCHUNKW  (CELLS / 32)          // 50,176 warp-chunks (32 cells each)
#define STAGES   3

#define WCHUNK_FLOATS  (32 * CH)             // 960 floats per tensor
#define WSTAGE_FLOATS  (2 * WCHUNK_FLOATS)   // 1920 (pred then tgt)
#define WSTAGE_BYTES   (WSTAGE_FLOATS * 4)   // 7680
#define V4_PER_WSTAGE  (WSTAGE_FLOATS / 4)   // 480
#define V4_ITERS       (V4_PER_WSTAGE / 32)  // 15 float4 per lane

#define SMEM_BYTES (NW_BLK * STAGES * WSTAGE_BYTES)  // 92,160

#define LAMBDA_COORD 5.0f
#define LAMBDA_NOOBJ 0.5f

__global__ void zero_out_kernel(float* out) { out[0] = 0.0f; }

__device__ __forceinline__ float sq(float x) { return x * x; }

__device__ __forceinline__ void issue_wchunk(
    const float* __restrict__ pred, const float* __restrict__ tgt,
    float* stage, int wchunk, int lane)
{
    if (wchunk < NCHUNKW) {
        const char* pb = (const char*)(pred + (size_t)wchunk * WCHUNK_FLOATS);
        const char* tb = (const char*)(tgt  + (size_t)wchunk * WCHUNK_FLOATS);
        uint32_t sb = (uint32_t)__cvta_generic_to_shared(stage);
        #pragma unroll
        for (int k = 0; k < V4_ITERS; ++k) {
            int i = lane + k * 32;                       // 0..479
            const char* src = (i < WCHUNK_FLOATS / 4)
                ? (pb + (size_t)i * 16)
                : (tb + (size_t)(i - WCHUNK_FLOATS / 4) * 16);
            asm volatile("cp.async.cg.shared.global [%0], [%1], 16;\n"
                         :: "r"(sb + i * 16), "l"(src));
        }
    }
    asm volatile("cp.async.commit_group;\n");
}

__device__ __forceinline__ float cell_loss(const float* stage, int lane)
{
    // lane base byte offsets are 8-aligned (lane*120) -> float2 loads
    const float2* p = reinterpret_cast<const float2*>(stage + lane * CH);
    const float2* t = reinterpret_cast<const float2*>(stage + WCHUNK_FLOATS + lane * CH);

    const float2 ta = t[0], tb = t[1], tc = t[2];
    const float t0 = ta.x, t1 = ta.y, t2 = tb.x, t3 = tb.y, t4 = tc.x;
    const float2 pa = p[0], pb = p[1], pc = p[2], pd = p[3], pe = p[4];
    const float p0 = pa.x, p1 = pa.y, p2v = pb.x, p3 = pb.y, p4 = pc.x;
    const float p5 = pc.y, p6 = pd.x, p7 = pd.y, p8 = pe.x, p9 = pe.y;
    const float t5 = tc.y;
    const float2 td = t[3], te = t[4];
    const float t6 = td.x, t7 = td.y, t8 = te.x, t9 = te.y;

    const float obj   = (t4 > 0.0f)  ? 1.0f : 0.0f;
    const float noobj = (t4 == 0.0f) ? 1.0f : 0.0f;
    const float tarea = (t2 - t0) * (t3 - t1);

    float iou1, iou2;
    {
        float lt0 = fmaxf(p0, t0), lt1 = fmaxf(p1, t1);
        float rb0 = fminf(p2v, t2), rb1 = fminf(p3, t3);
        float w = fmaxf(rb0 - lt0, 0.0f), h = fmaxf(rb1 - lt1, 0.0f);
        float inter = w * h;
        float a1 = (p2v - p0) * (p3 - p1);
        iou1 = inter / (a1 + tarea - inter);
    }
    {
        float lt0 = fmaxf(p5, t0), lt1 = fmaxf(p6, t1);
        float rb0 = fminf(p7, t2), rb1 = fminf(p8, t3);
        float w = fmaxf(rb0 - lt0, 0.0f), h = fmaxf(rb1 - lt1, 0.0f);
        float inter = w * h;
        float a1 = (p7 - p5) * (p8 - p6);
        iou2 = inter / (a1 + tarea - inter);
    }

    // jnp.argmax tie -> first index: box 1 wins when iou1 >= iou2
    const float c0 = (iou1 >= iou2) ? 1.0f : 0.0f;
    const float c1 = 1.0f - c0;

    float l1 = (sq(p0 - t0) + sq(p1 - t1)) * c0
             + (sq(p5 - t5) + sq(p6 - t6)) * c1;

    float l2 = (sq(sqrtf(p2v) - sqrtf(t2)) + sq(sqrtf(p3) - sqrtf(t3))) * c0
             + (sq(sqrtf(p7)  - sqrtf(t7)) + sq(sqrtf(p8) - sqrtf(t8))) * c1;

    float conf = sq(p4 - t4) * c0 + sq(p9 - t9) * c1;

    float l5 = 0.0f;
    #pragma unroll
    for (int k = 5; k < 15; ++k) {   // float2 pairs covering channels 10..29
        float2 pp = p[k], tt = t[k];
        l5 += sq(pp.x - tt.x) + sq(pp.y - tt.y);
    }

    return obj * (LAMBDA_COORD * (l1 + l2) + conf + l5)
         + LAMBDA_NOOBJ * noobj * conf;
}

extern __shared__ float smem[];   // NW_BLK * STAGES * WSTAGE_FLOATS

__global__ __launch_bounds__(TPB) void yolo_loss_kernel(
    const float* __restrict__ pred,
    const float* __restrict__ tgt,
    float* __restrict__ out)
{
    const int tid  = threadIdx.x;
    const int lane = tid & 31;
    const int w    = tid >> 5;
    const int gw   = blockIdx.x * NW_BLK + w;     // global warp id

    float* wbase = smem + w * (STAGES * WSTAGE_FLOATS);

    // Prologue: fill this warp's pipeline
    #pragma unroll
    for (int s = 0; s < STAGES; ++s)
        issue_wchunk(pred, tgt, wbase + s * WSTAGE_FLOATS, gw + s * NWARPS, lane);

    float acc = 0.0f;
    int si = 0;

    for (int c = gw; c < NCHUNKW; c += NWARPS) {
        asm volatile("cp.async.wait_group %0;\n" :: "n"(STAGES - 1));
        __syncwarp();

        float* stage = wbase + si * WSTAGE_FLOATS;
        acc += cell_loss(stage, lane);

        __syncwarp();
        issue_wchunk(pred, tgt, stage, c + STAGES * NWARPS, lane);

        si = (si + 1 == STAGES) ? 0 : si + 1;
    }

    // Drain outstanding groups so smem reuse below is safe
    asm volatile("cp.async.wait_group 0;\n");
    __syncthreads();

    // Warp reduce -> smem -> single atomic per block
    #pragma unroll
    for (int o = 16; o > 0; o >>= 1)
        acc += __shfl_xor_sync(0xFFFFFFFFu, acc, o);

    if (lane == 0) smem[w] = acc;
    __syncthreads();

    if (tid == 0) {
        float s = smem[0] + smem[1] + smem[2] + smem[3];
        atomicAdd(out, s);
    }
}

extern "C" void kernel_launch(void* const* d_in, const int* in_sizes, int n_in,
                              void* d_out, int out_size)
{
    const float* pred = (const float*)d_in[0];
    const float* tgt  = (const float*)d_in[1];
    float* out = (float*)d_out;

    static bool attr_set = false;
    if (!attr_set) {
        cudaFuncSetAttribute(yolo_loss_kernel,
                             cudaFuncAttributeMaxDynamicSharedMemorySize,
                             SMEM_BYTES);
        attr_set = true;
    }

    zero_out_kernel<<<1, 1>>>(out);
    yolo_loss_kernel<<<GRID_B, TPB, SMEM_BYTES>>>(pred, tgt, out);
}

// round 5
// speedup vs baseline: 1.0279x; 1.0279x over previous
#include <cuda_runtime.h>
#include <cstdint>

// YOLO-v1 loss: pred/target (2048, 28, 28, 30) fp32 -> scalar fp32.
// Persistent small blocks (TPB=64) + 2-stage (double-buffered) cp.async
// pipeline; 7 blocks/SM (14 warps/SM) -- occupancy raised by shrinking
// smem-per-warp. Thread-per-cell compute from smem via float2; per-thread
// accumulator; one atomicAdd per block.

#define CELLS   (2048 * 28 * 28)        // 1,605,632
#define CH      30
#define TPB     64
#define CPC     64                      // cells per chunk (= TPB)
#define NCHUNK  (CELLS / CPC)           // 25,088
#define BLK_PER_SM 7
#define GRID_B  (148 * BLK_PER_SM)      // 1036 persistent blocks
#define STAGES  2

#define CHUNK_FLOATS   (CPC * CH)            // 1920 floats per tensor
#define STAGE_FLOATS   (2 * CHUNK_FLOATS)    // 3840 (pred then tgt)
#define STAGE_BYTES    (STAGE_FLOATS * 4)    // 15,360
#define VEC4_PER_STAGE (STAGE_FLOATS / 4)    // 960
#define V4_ITERS       (VEC4_PER_STAGE / TPB) // 15

#define SMEM_BYTES (STAGES * STAGE_BYTES)    // 30,720 B/block

#define LAMBDA_COORD 5.0f
#define LAMBDA_NOOBJ 0.5f

__global__ void zero_out_kernel(float* out) { out[0] = 0.0f; }

__device__ __forceinline__ float sq(float x) { return x * x; }

__device__ __forceinline__ void issue_chunk(
    const float* __restrict__ pred, const float* __restrict__ tgt,
    float* stage, int chunk, int tid)
{
    if (chunk < NCHUNK) {
        const char* pb = (const char*)(pred + (size_t)chunk * CHUNK_FLOATS);
        const char* tb = (const char*)(tgt  + (size_t)chunk * CHUNK_FLOATS);
        uint32_t sb = (uint32_t)__cvta_generic_to_shared(stage);
        #pragma unroll
        for (int k = 0; k < V4_ITERS; ++k) {
            int i = tid + k * TPB;                      // 0..959
            const char* src = (i < CHUNK_FLOATS / 4)
                ? (pb + (size_t)i * 16)
                : (tb + (size_t)(i - CHUNK_FLOATS / 4) * 16);
            asm volatile("cp.async.cg.shared.global [%0], [%1], 16;\n"
                         :: "r"(sb + i * 16), "l"(src));
        }
    }
    asm volatile("cp.async.commit_group;\n");
}

__device__ __forceinline__ float cell_loss(const float* stage, int tid)
{
    // per-cell base byte offsets are 8-aligned (tid*120) -> float2 loads
    const float2* p = reinterpret_cast<const float2*>(stage + tid * CH);
    const float2* t = reinterpret_cast<const float2*>(stage + CHUNK_FLOATS + tid * CH);

    const float2 ta = t[0], tb = t[1], tc = t[2], td = t[3], te = t[4];
    const float t0 = ta.x, t1 = ta.y, t2 = tb.x, t3 = tb.y, t4 = tc.x;
    const float t5 = tc.y, t6 = td.x, t7 = td.y, t8 = te.x, t9 = te.y;
    const float2 pa = p[0], pb = p[1], pc = p[2], pd = p[3], pe = p[4];
    const float p0 = pa.x, p1 = pa.y, p2v = pb.x, p3 = pb.y, p4 = pc.x;
    const float p5 = pc.y, p6 = pd.x, p7 = pd.y, p8 = pe.x, p9 = pe.y;

    const float obj   = (t4 > 0.0f)  ? 1.0f : 0.0f;
    const float noobj = (t4 == 0.0f) ? 1.0f : 0.0f;
    const float tarea = (t2 - t0) * (t3 - t1);

    float iou1, iou2;
    {
        float lt0 = fmaxf(p0, t0), lt1 = fmaxf(p1, t1);
        float rb0 = fminf(p2v, t2), rb1 = fminf(p3, t3);
        float w = fmaxf(rb0 - lt0, 0.0f), h = fmaxf(rb1 - lt1, 0.0f);
        float inter = w * h;
        float a1 = (p2v - p0) * (p3 - p1);
        iou1 = inter / (a1 + tarea - inter);
    }
    {
        float lt0 = fmaxf(p5, t0), lt1 = fmaxf(p6, t1);
        float rb0 = fminf(p7, t2), rb1 = fminf(p8, t3);
        float w = fmaxf(rb0 - lt0, 0.0f), h = fmaxf(rb1 - lt1, 0.0f);
        float inter = w * h;
        float a1 = (p7 - p5) * (p8 - p6);
        iou2 = inter / (a1 + tarea - inter);
    }

    // jnp.argmax tie -> first index: box 1 wins when iou1 >= iou2
    const float c0 = (iou1 >= iou2) ? 1.0f : 0.0f;
    const float c1 = 1.0f - c0;

    float l1 = (sq(p0 - t0) + sq(p1 - t1)) * c0
             + (sq(p5 - t5) + sq(p6 - t6)) * c1;

    float l2 = (sq(sqrtf(p2v) - sqrtf(t2)) + sq(sqrtf(p3) - sqrtf(t3))) * c0
             + (sq(sqrtf(p7)  - sqrtf(t7)) + sq(sqrtf(p8) - sqrtf(t8))) * c1;

    float conf = sq(p4 - t4) * c0 + sq(p9 - t9) * c1;

    float l5 = 0.0f;
    #pragma unroll
    for (int k = 5; k < 15; ++k) {   // float2 pairs covering channels 10..29
        float2 pp = p[k], tt = t[k];
        l5 += sq(pp.x - tt.x) + sq(pp.y - tt.y);
    }

    return obj * (LAMBDA_COORD * (l1 + l2) + conf + l5)
         + LAMBDA_NOOBJ * noobj * conf;
}

extern __shared__ float smem[];   // STAGES * STAGE_FLOATS

__global__ __launch_bounds__(TPB, BLK_PER_SM) void yolo_loss_kernel(
    const float* __restrict__ pred,
    const float* __restrict__ tgt,
    float* __restrict__ out)
{
    const int tid = threadIdx.x;
    const int bid = blockIdx.x;

    // Prologue: fill both buffers
    #pragma unroll
    for (int s = 0; s < STAGES; ++s)
        issue_chunk(pred, tgt, smem + s * STAGE_FLOATS, bid + s * GRID_B, tid);

    float acc = 0.0f;
    int si = 0;

    for (int c = bid; c < NCHUNK; c += GRID_B) {
        // Wait for the older group (this stage); the newer one keeps loading.
        asm volatile("cp.async.wait_group %0;\n" :: "n"(STAGES - 1));
        __syncthreads();

        float* stage = smem + si * STAGE_FLOATS;
        acc += cell_loss(stage, tid);

        __syncthreads();   // both warps done reading before refill
        issue_chunk(pred, tgt, stage, c + STAGES * GRID_B, tid);

        si ^= 1;
    }

    // Drain outstanding groups so smem reuse below is safe
    asm volatile("cp.async.wait_group 0;\n");
    __syncthreads();

    // Warp reduce -> smem -> single atomic per block
    #pragma unroll
    for (int o = 16; o > 0; o >>= 1)
        acc += __shfl_xor_sync(0xFFFFFFFFu, acc, o);

    if ((tid & 31) == 0) smem[tid >> 5] = acc;
    __syncthreads();

    if (tid == 0)
        atomicAdd(out, smem[0] + smem[1]);
}

extern "C" void kernel_launch(void* const* d_in, const int* in_sizes, int n_in,
                              void* d_out, int out_size)
{
    const float* pred = (const float*)d_in[0];
    const float* tgt  = (const float*)d_in[1];
    float* out = (float*)d_out;

    static bool attr_set = false;
    if (!attr_set) {
        cudaFuncSetAttribute(yolo_loss_kernel,
                             cudaFuncAttributeMaxDynamicSharedMemorySize,
                             SMEM_BYTES);
        attr_set = true;
    }

    zero_out_kernel<<<1, 1>>>(out);
    yolo_loss_kernel<<<GRID_B, TPB, SMEM_BYTES>>>(pred, tgt, out);
}

// round 7
// speedup vs baseline: 1.0348x; 1.0068x over previous
#include <cuda_runtime.h>
#include <cstdint>

// YOLO-v1 loss: pred/target (2048, 28, 28, 30) fp32 -> scalar fp32.
// Persistent small blocks (TPB=64) + double-buffered cp.async pipeline.
// GRID_B=896 divides NCHUNK exactly (28 chunks/block, no tail imbalance).
// Single kernel: blocks accumulate into __device__ scratch; the last block
// (arrival counter) writes out[0] and resets state (graph-replay safe).

#define CELLS   (2048 * 28 * 28)        // 1,605,632
#define CH      30
#define TPB     64
#define CPC     64                      // cells per chunk (= TPB)
#define NCHUNK  (CELLS / CPC)           // 25,088
#define GRID_B  896                     // 25,088 / 896 = 28 exactly
#define STAGES  2

#define CHUNK_FLOATS   (CPC * CH)             // 1920 floats per tensor
#define STAGE_FLOATS   (2 * CHUNK_FLOATS)     // 3840 (pred then tgt)
#define STAGE_BYTES    (STAGE_FLOATS * 4)     // 15,360
#define VEC4_PER_STAGE (STAGE_FLOATS / 4)     // 960
#define V4_ITERS       (VEC4_PER_STAGE / TPB) // 15

#define SMEM_BYTES (STAGES * STAGE_BYTES)     // 30,720 B/block

#define LAMBDA_COORD 5.0f
#define LAMBDA_NOOBJ 0.5f

__device__ float        g_scratch = 0.0f;
__device__ unsigned int g_count   = 0;

__device__ __forceinline__ float sq(float x) { return x * x; }

__device__ __forceinline__ void issue_chunk(
    const float* __restrict__ pred, const float* __restrict__ tgt,
    float* stage, int chunk, int tid)
{
    if (chunk < NCHUNK) {
        const char* pb = (const char*)(pred + (size_t)chunk * CHUNK_FLOATS);
        const char* tb = (const char*)(tgt  + (size_t)chunk * CHUNK_FLOATS);
        uint32_t sb = (uint32_t)__cvta_generic_to_shared(stage);
        #pragma unroll
        for (int k = 0; k < V4_ITERS; ++k) {
            int i = tid + k * TPB;                      // 0..959
            const char* src = (i < CHUNK_FLOATS / 4)
                ? (pb + (size_t)i * 16)
                : (tb + (size_t)(i - CHUNK_FLOATS / 4) * 16);
            asm volatile("cp.async.cg.shared.global [%0], [%1], 16;\n"
                         :: "r"(sb + i * 16), "l"(src));
        }
    }
    asm volatile("cp.async.commit_group;\n");
}

__device__ __forceinline__ float cell_loss(const float* stage, int tid)
{
    // per-cell base byte offsets are 8-aligned (tid*120) -> float2 loads
    const float2* p = reinterpret_cast<const float2*>(stage + tid * CH);
    const float2* t = reinterpret_cast<const float2*>(stage + CHUNK_FLOATS + tid * CH);

    const float2 ta = t[0], tb = t[1], tc = t[2], td = t[3], te = t[4];
    const float t0 = ta.x, t1 = ta.y, t2 = tb.x, t3 = tb.y, t4 = tc.x;
    const float t5 = tc.y, t6 = td.x, t7 = td.y, t8 = te.x, t9 = te.y;
    const float2 pa = p[0], pb = p[1], pc = p[2], pd = p[3], pe = p[4];
    const float p0 = pa.x, p1 = pa.y, p2v = pb.x, p3 = pb.y, p4 = pc.x;
    const float p5 = pc.y, p6 = pd.x, p7 = pd.y, p8 = pe.x, p9 = pe.y;

    const float obj   = (t4 > 0.0f)  ? 1.0f : 0.0f;
    const float noobj = (t4 == 0.0f) ? 1.0f : 0.0f;
    const float tarea = (t2 - t0) * (t3 - t1);

    float iou1, iou2;
    {
        float lt0 = fmaxf(p0, t0), lt1 = fmaxf(p1, t1);
        float rb0 = fminf(p2v, t2), rb1 = fminf(p3, t3);
        float w = fmaxf(rb0 - lt0, 0.0f), h = fmaxf(rb1 - lt1, 0.0f);
        float inter = w * h;
        float a1 = (p2v - p0) * (p3 - p1);
        iou1 = inter / (a1 + tarea - inter);
    }
    {
        float lt0 = fmaxf(p5, t0), lt1 = fmaxf(p6, t1);
        float rb0 = fminf(p7, t2), rb1 = fminf(p8, t3);
        float w = fmaxf(rb0 - lt0, 0.0f), h = fmaxf(rb1 - lt1, 0.0f);
        float inter = w * h;
        float a1 = (p7 - p5) * (p8 - p6);
        iou2 = inter / (a1 + tarea - inter);
    }

    // jnp.argmax tie -> first index: box 1 wins when iou1 >= iou2
    const float c0 = (iou1 >= iou2) ? 1.0f : 0.0f;
    const float c1 = 1.0f - c0;

    float l1 = (sq(p0 - t0) + sq(p1 - t1)) * c0
             + (sq(p5 - t5) + sq(p6 - t6)) * c1;

    float l2 = (sq(sqrtf(p2v) - sqrtf(t2)) + sq(sqrtf(p3) - sqrtf(t3))) * c0
             + (sq(sqrtf(p7)  - sqrtf(t7)) + sq(sqrtf(p8) - sqrtf(t8))) * c1;

    float conf = sq(p4 - t4) * c0 + sq(p9 - t9) * c1;

    float l5 = 0.0f;
    #pragma unroll
    for (int k = 5; k < 15; ++k) {   // float2 pairs covering channels 10..29
        float2 pp = p[k], tt = t[k];
        l5 += sq(pp.x - tt.x) + sq(pp.y - tt.y);
    }

    return obj * (LAMBDA_COORD * (l1 + l2) + conf + l5)
         + LAMBDA_NOOBJ * noobj * conf;
}

extern __shared__ float smem[];   // STAGES * STAGE_FLOATS

__global__ __launch_bounds__(TPB, 7) void yolo_loss_kernel(
    const float* __restrict__ pred,
    const float* __restrict__ tgt,
    float* __restrict__ out)
{
    const int tid = threadIdx.x;
    const int bid = blockIdx.x;

    // Prologue: fill both buffers
    #pragma unroll
    for (int s = 0; s < STAGES; ++s)
        issue_chunk(pred, tgt, smem + s * STAGE_FLOATS, bid + s * GRID_B, tid);

    float acc = 0.0f;
    int si = 0;

    #pragma unroll 1
    for (int c = bid; c < NCHUNK; c += GRID_B) {
        // Wait for the older group (this stage); the newer one keeps loading.
        asm volatile("cp.async.wait_group %0;\n" :: "n"(STAGES - 1));
        __syncthreads();

        float* stage = smem + si * STAGE_FLOATS;
        acc += cell_loss(stage, tid);

        __syncthreads();   // both warps done reading before refill
        issue_chunk(pred, tgt, stage, c + STAGES * GRID_B, tid);

        si ^= 1;
    }

    // Drain outstanding groups so smem reuse below is safe
    asm volatile("cp.async.wait_group 0;\n");
    __syncthreads();

    // Warp reduce -> smem -> block partial
    #pragma unroll
    for (int o = 16; o > 0; o >>= 1)
        acc += __shfl_xor_sync(0xFFFFFFFFu, acc, o);

    if ((tid & 31) == 0) smem[tid >> 5] = acc;
    __syncthreads();

    if (tid == 0) {
        float partial = smem[0] + smem[1];
        atomicAdd(&g_scratch, partial);
        __threadfence();
        unsigned int old = atomicAdd(&g_count, 1u);
        if (old == GRID_B - 1) {
            // All partials are visible (each block fenced before its count).
            float total = atomicAdd(&g_scratch, 0.0f);  // atomic read
            out[0] = total;
            // Reset state for the next graph replay (deterministic).
            g_scratch = 0.0f;
            __threadfence();
            g_count = 0u;
        }
    }
}

extern "C" void kernel_launch(void* const* d_in, const int* in_sizes, int n_in,
                              void* d_out, int out_size)
{
    const float* pred = (const float*)d_in[0];
    const float* tgt  = (const float*)d_in[1];
    float* out = (float*)d_out;

    static bool attr_set = false;
    if (!attr_set) {
        cudaFuncSetAttribute(yolo_loss_kernel,
                             cudaFuncAttributeMaxDynamicSharedMemorySize,
                             SMEM_BYTES);
        attr_set = true;
    }

    yolo_loss_kernel<<<GRID_B, TPB, SMEM_BYTES>>>(pred, tgt, out);
}